// round 14
// baseline (speedup 1.0000x reference)
#include <cuda_runtime.h>
#include <cstdint>

#define B_EX   16384
#define NEG    10
#define NVAL   (NEG + 1)      // 11 partial values per example (pos + 10 neg)
#define WARPS_PER_BLOCK 8
#define THREADS (WARPS_PER_BLOCK * 32)
#define NBLOCKS (B_EX / WARPS_PER_BLOCK)   // 2048
#define NLOSS   (WARPS_PER_BLOCK * NVAL)   // 88 loss terms per block
#define RING_DEPTH 4

// Scratch (allocation-free __device__ globals per harness rules)
__device__ float        g_partials[NBLOCKS];
__device__ unsigned int g_count = 0;

__device__ __forceinline__ float log_sigmoid(float x) {
    return fminf(x, 0.0f) - log1pf(expf(-fabsf(x)));
}

__device__ __forceinline__ float dot4(float4 a, float4 b) {
    return a.x * b.x + a.y * b.y + a.z * b.z + a.w * b.w;
}

__device__ __forceinline__ void cp_async16(void* dst_smem, const void* src_gmem) {
    uint32_t d = (uint32_t)__cvta_generic_to_shared(dst_smem);
    asm volatile("cp.async.cg.shared.global [%0], [%1], 16;" :: "r"(d), "l"(src_gmem));
}
#define CP_COMMIT() asm volatile("cp.async.commit_group;" ::: "memory")
__device__ __forceinline__ void cp_wait(int n) {   // n is constant after unroll
    switch (n) {
        case 0: asm volatile("cp.async.wait_group 0;" ::: "memory"); break;
        case 1: asm volatile("cp.async.wait_group 1;" ::: "memory"); break;
        case 2: asm volatile("cp.async.wait_group 2;" ::: "memory"); break;
        default: asm volatile("cp.async.wait_group 3;" ::: "memory"); break;
    }
}

__global__ void __launch_bounds__(THREADS)
w2v_fused_kernel(const int*    __restrict__ input_word,
                 const int*    __restrict__ context_word,
                 const int*    __restrict__ noise_words,
                 const float4* __restrict__ W_in,
                 const float4* __restrict__ W_ctx,
                 float*        __restrict__ out)
{
    // Per-warp 4-slot ring for streaming noise rows (registers NOT consumed).
    __shared__ float4 ring[WARPS_PER_BLOCK][RING_DEPTH][32];   // 16 KB
    // Per-lane partials, 33-float stride: conflict-free write + transposed read.
    __shared__ float sp[WARPS_PER_BLOCK][NVAL][33];            // 11.6 KB
    __shared__ float s_vals[NLOSS];
    __shared__ bool  s_is_last;

    const int lane    = threadIdx.x & 31;
    const int warp_in = threadIdx.x >> 5;
    const int b       = blockIdx.x * WARPS_PER_BLOCK + warp_in;   // example id

    // Noise indices first (gate 10 of 12 gathers), vectorized int2.
    const int2* np = (const int2*)(noise_words + b * NEG);
    int2 np0 = np[0], np1 = np[1], np2 = np[2], np3 = np[3], np4 = np[4];
    const int ci = input_word[b];
    const int xi = context_word[b];
    const int nidx[NEG] = { np0.x, np0.y, np1.x, np1.y, np2.x,
                            np2.y, np3.x, np3.y, np4.x, np4.y };

    // Register gathers for the two rows used directly.
    float4 c = W_in [(size_t)ci * 32 + lane];
    float4 x = W_ctx[(size_t)xi * 32 + lane];

    // Ring prologue: noise rows 0..3 in flight via cp.async (one group per row).
#pragma unroll
    for (int r = 0; r < RING_DEPTH; r++) {
        cp_async16(&ring[warp_in][r][lane], &W_ctx[(size_t)nidx[r] * 32 + lane]);
        CP_COMMIT();
    }

    // Positive dot while the ring fills.
    sp[warp_in][0][lane] = dot4(c, x);

    // Steady state: consume row k, refill slot with row k+4.
    // Groups complete in commit order; before consuming row k, groups <= k must
    // be done. Committed so far = 4 + min(k,6)  ->  allowed pending:
    //   k<=6: 3,  k=7: 2,  k=8: 1,  k=9: 0.
#pragma unroll
    for (int k = 0; k < NEG; k++) {
        cp_wait(k <= 6 ? 3 : 9 - k);
        float4 nv = ring[warp_in][k & (RING_DEPTH - 1)][lane];   // own bytes only
        // Refill AFTER the read; cp.async's global fetch (>=250cy) cannot land
        // before the just-issued LDS (~29cy) completes.
        if (k < NEG - RING_DEPTH) {
            cp_async16(&ring[warp_in][k & (RING_DEPTH - 1)][lane],
                       &W_ctx[(size_t)nidx[k + RING_DEPTH] * 32 + lane]);
            CP_COMMIT();
        }
        sp[warp_in][1 + k][lane] = dot4(c, nv);
    }
    __syncthreads();

    // 88 threads: each sums one (example, k) column of 32 partials
    // (fixed-order serial sum -> deterministic) and applies log-sigmoid.
    const int t = threadIdx.x;
    if (t < NLOSS) {
        const int ex = t / NVAL;
        const int k  = t % NVAL;
        float s = 0.0f;
#pragma unroll
        for (int j = 0; j < 32; j++)
            s += sp[ex][k][j];
        s_vals[t] = (k == 0) ? -log_sigmoid(s) : -log_sigmoid(-s);
    }
    __syncthreads();

    // Warp 0 reduces the 88 loss terms (fixed order: deterministic).
    if (warp_in == 0) {
        float v = 0.0f;
#pragma unroll
        for (int j = 0; j < 3; j++) {
            int idx = lane + j * 32;
            if (idx < NLOSS) v += s_vals[idx];
        }
#pragma unroll
        for (int off = 16; off > 0; off >>= 1)
            v += __shfl_xor_sync(0xffffffffu, v, off);

        if (lane == 0) {
            g_partials[blockIdx.x] = v;
            unsigned int cnt;
            asm volatile("atom.release.gpu.global.add.u32 %0, [%1], 1;"
                         : "=r"(cnt) : "l"(&g_count) : "memory");
            s_is_last = (cnt == (unsigned int)(NBLOCKS - 1));
        }
    }
    __syncthreads();

    // ---- fused finalize: last block reduces all block partials ----
    if (s_is_last) {
        asm volatile("fence.acquire.gpu;" ::: "memory");
        volatile float* gp = g_partials;
        float tacc = 0.0f;
#pragma unroll
        for (int j = 0; j < NBLOCKS / THREADS; j++)     // 8 iterations
            tacc += gp[threadIdx.x + j * THREADS];

        __shared__ float s_red[THREADS];
        s_red[threadIdx.x] = tacc;
        __syncthreads();
#pragma unroll
        for (int step = THREADS / 2; step > 0; step >>= 1) {
            if (threadIdx.x < step) s_red[threadIdx.x] += s_red[threadIdx.x + step];
            __syncthreads();
        }
        if (threadIdx.x == 0) {
            out[0]  = s_red[0] / (float)B_EX;
            g_count = 0;                   // reset for next graph replay
        }
    }
}

extern "C" void kernel_launch(void* const* d_in, const int* in_sizes, int n_in,
                              void* d_out, int out_size)
{
    const int*    input_word   = (const int*)   d_in[0];
    const int*    context_word = (const int*)   d_in[1];
    const int*    noise_words  = (const int*)   d_in[2];
    const float4* W_in         = (const float4*)d_in[3];
    const float4* W_ctx        = (const float4*)d_in[4];
    float* out = (float*)d_out;

    w2v_fused_kernel<<<NBLOCKS, THREADS>>>(input_word, context_word,
                                           noise_words, W_in, W_ctx, out);
}

// round 15
// speedup vs baseline: 1.0019x; 1.0019x over previous
#include <cuda_runtime.h>

#define B_EX   16384
#define NEG    10
#define NVAL   (NEG + 1)      // 11 values per example (pos + 10 neg)
#define WARPS_PER_BLOCK 8
#define THREADS (WARPS_PER_BLOCK * 32)
#define NBLOCKS (B_EX / WARPS_PER_BLOCK)   // 2048

// Scratch (allocation-free __device__ globals per harness rules)
__device__ float        g_partials[NBLOCKS];
__device__ unsigned int g_count = 0;

__device__ __forceinline__ float log_sigmoid(float x) {
    return fminf(x, 0.0f) - log1pf(expf(-fabsf(x)));
}

__device__ __forceinline__ float dot4(float4 a, float4 b) {
    return a.x * b.x + a.y * b.y + a.z * b.z + a.w * b.w;
}

__global__ void __launch_bounds__(THREADS)
w2v_fused_kernel(const int*    __restrict__ input_word,
                 const int*    __restrict__ context_word,
                 const int*    __restrict__ noise_words,
                 const float4* __restrict__ W_in,
                 const float4* __restrict__ W_ctx,
                 float*        __restrict__ out)
{
    // Per-warp PRIVATE pad: stride 33 -> lane-major write and transposed
    // column read are both bank-conflict-free. No cross-warp sharing.
    __shared__ float sp[WARPS_PER_BLOCK][NVAL][33];   // 11.6 KB
    __shared__ float s_warp[WARPS_PER_BLOCK];
    __shared__ bool  s_is_last;

    const int lane    = threadIdx.x & 31;
    const int warp_in = threadIdx.x >> 5;
    const int b       = blockIdx.x * WARPS_PER_BLOCK + warp_in;   // example id

    // Noise indices first (they gate 10 of 12 gathers), vectorized int2.
    const int2* np = (const int2*)(noise_words + b * NEG);
    int2 np0 = np[0], np1 = np[1], np2 = np[2], np3 = np[3], np4 = np[4];
    const int ci = input_word[b];
    const int xi = context_word[b];
    const int nidx[NEG] = { np0.x, np0.y, np1.x, np1.y, np2.x,
                            np2.y, np3.x, np3.y, np4.x, np4.y };

    // Row = 128 floats = 32 float4; lane l owns float4 #l of each row.
    // All 12 gathers issued before any math.
    float4 nv[NEG];
#pragma unroll
    for (int k = 0; k < NEG; k++)
        nv[k] = W_ctx[(size_t)nidx[k] * 32 + lane];
    float4 c = W_in [(size_t)ci * 32 + lane];
    float4 x = W_ctx[(size_t)xi * 32 + lane];

    // Per-lane partial dots -> this warp's private pad.
    sp[warp_in][0][lane] = dot4(c, x);
#pragma unroll
    for (int k = 0; k < NEG; k++)
        sp[warp_in][1 + k][lane] = dot4(c, nv[k]);
    __syncwarp();        // warp-local only — no cross-warp gather coupling

    // Lanes 0..10: fixed-order column sum (stride-33: conflict-free) + loss term.
    float term = 0.0f;
    if (lane < NVAL) {
        float s = 0.0f;
#pragma unroll
        for (int j = 0; j < 32; j++)
            s += sp[warp_in][lane][j];
        term = (lane == 0) ? -log_sigmoid(s) : -log_sigmoid(-s);
    }
    // Butterfly over 32 lanes (lanes >= 11 contribute 0): deterministic.
#pragma unroll
    for (int off = 16; off > 0; off >>= 1)
        term += __shfl_xor_sync(0xffffffffu, term, off);

    if (lane == 0) s_warp[warp_in] = term;
    __syncthreads();     // the ONLY block-wide barrier on the main path

    if (threadIdx.x == 0) {
        float t = 0.0f;
#pragma unroll
        for (int i = 0; i < WARPS_PER_BLOCK; i++) t += s_warp[i];
        g_partials[blockIdx.x] = t;
        unsigned int cnt;
        asm volatile("atom.release.gpu.global.add.u32 %0, [%1], 1;"
                     : "=r"(cnt) : "l"(&g_count) : "memory");
        s_is_last = (cnt == (unsigned int)(NBLOCKS - 1));
    }
    __syncthreads();

    // ---- fused finalize: last block reduces all block partials ----
    if (s_is_last) {
        asm volatile("fence.acquire.gpu;" ::: "memory");
        volatile float* gp = g_partials;
        float tacc = 0.0f;
#pragma unroll
        for (int j = 0; j < NBLOCKS / THREADS; j++)     // 8 iterations
            tacc += gp[threadIdx.x + j * THREADS];

        __shared__ float s_red[THREADS];
        s_red[threadIdx.x] = tacc;
        __syncthreads();
#pragma unroll
        for (int step = THREADS / 2; step > 0; step >>= 1) {
            if (threadIdx.x < step) s_red[threadIdx.x] += s_red[threadIdx.x + step];
            __syncthreads();
        }
        if (threadIdx.x == 0) {
            out[0]  = s_red[0] / (float)B_EX;
            g_count = 0;                   // reset for next graph replay
        }
    }
}

extern "C" void kernel_launch(void* const* d_in, const int* in_sizes, int n_in,
                              void* d_out, int out_size)
{
    const int*    input_word   = (const int*)   d_in[0];
    const int*    context_word = (const int*)   d_in[1];
    const int*    noise_words  = (const int*)   d_in[2];
    const float4* W_in         = (const float4*)d_in[3];
    const float4* W_ctx        = (const float4*)d_in[4];
    float* out = (float*)d_out;

    w2v_fused_kernel<<<NBLOCKS, THREADS>>>(input_word, context_word,
                                           noise_words, W_in, W_ctx, out);
}

// round 16
// speedup vs baseline: 1.1078x; 1.1056x over previous
#include <cuda_runtime.h>

#define B_EX   16384
#define NEG    10
#define NVAL   (NEG + 1)      // 11 partial values per example (pos + 10 neg)
#define WARPS_PER_BLOCK 8
#define THREADS (WARPS_PER_BLOCK * 32)
#define NBLOCKS (B_EX / WARPS_PER_BLOCK)   // 2048
#define NLOSS   (WARPS_PER_BLOCK * NVAL)   // 88 loss terms per block

// Scratch (allocation-free __device__ globals per harness rules)
__device__ float        g_partials[NBLOCKS];
__device__ unsigned int g_count = 0;

__device__ __forceinline__ float log_sigmoid(float x) {
    return fminf(x, 0.0f) - log1pf(expf(-fabsf(x)));
}

__device__ __forceinline__ float dot4(float4 a, float4 b) {
    return a.x * b.x + a.y * b.y + a.z * b.z + a.w * b.w;
}

__global__ void __launch_bounds__(THREADS)
w2v_fused_kernel(const int*    __restrict__ input_word,
                 const int*    __restrict__ context_word,
                 const int*    __restrict__ noise_words,
                 const float4* __restrict__ W_in,
                 const float4* __restrict__ W_ctx,
                 float*        __restrict__ out)
{
    // Per-lane partials, padded to 33 floats so the transposed read
    // (fixed j, thread-varying row) is bank-conflict-free.
    __shared__ float sp[WARPS_PER_BLOCK][NVAL][33];   // 11.6 KB
    __shared__ float s_vals[NLOSS];                   // 88 loss terms
    __shared__ bool  s_is_last;

    const int lane    = threadIdx.x & 31;
    const int warp_in = threadIdx.x >> 5;
    const int b       = blockIdx.x * WARPS_PER_BLOCK + warp_in;   // example id

    // Noise indices first (they gate 10 of 12 gathers), vectorized int2:
    // noise_words + b*10 is 8-byte aligned for every b.
    const int2* np = (const int2*)(noise_words + b * NEG);
    int2 np0 = np[0], np1 = np[1], np2 = np[2], np3 = np[3], np4 = np[4];
    const int ci = input_word[b];
    const int xi = context_word[b];
    const int nidx[NEG] = { np0.x, np0.y, np1.x, np1.y, np2.x,
                            np2.y, np3.x, np3.y, np4.x, np4.y };

    // Row = 128 floats = 32 float4; lane l owns float4 #l of each row.
    // All 12 gathers issued before any math (max MLP at the 32-reg /
    // 8-block-per-SM operating point: ~88% occupancy carries the hiding).
    float4 nv[NEG];
#pragma unroll
    for (int k = 0; k < NEG; k++)
        nv[k] = W_ctx[(size_t)nidx[k] * 32 + lane];
    float4 c = W_in [(size_t)ci * 32 + lane];
    float4 x = W_ctx[(size_t)xi * 32 + lane];

    // Per-lane partial dots -> smem (no per-warp shuffle butterflies:
    // minimum instruction mass epilogue, R8/R13 champion structure).
    sp[warp_in][0][lane] = dot4(c, x);
#pragma unroll
    for (int k = 0; k < NEG; k++)
        sp[warp_in][1 + k][lane] = dot4(c, nv[k]);
    __syncthreads();

    // 88 threads: each sums one (example, k) column of 32 partials.
    // Two independent chains halve the FADD dependency depth; order is
    // fixed -> deterministic across replays.
    const int t = threadIdx.x;
    if (t < NLOSS) {
        const int ex = t / NVAL;
        const int k  = t % NVAL;
        float sA = 0.0f, sB = 0.0f;
#pragma unroll
        for (int j = 0; j < 16; j++) {
            sA += sp[ex][k][j];
            sB += sp[ex][k][j + 16];
        }
        float s = sA + sB;
        s_vals[t] = (k == 0) ? -log_sigmoid(s) : -log_sigmoid(-s);
    }
    __syncthreads();

    // Warp 0 reduces the 88 loss terms (fixed order: deterministic).
    if (warp_in == 0) {
        float v = 0.0f;
#pragma unroll
        for (int j = 0; j < 3; j++) {
            int idx = lane + j * 32;
            if (idx < NLOSS) v += s_vals[idx];
        }
#pragma unroll
        for (int off = 16; off > 0; off >>= 1)
            v += __shfl_xor_sync(0xffffffffu, v, off);

        if (lane == 0) {
            g_partials[blockIdx.x] = v;
            unsigned int cnt;
            asm volatile("atom.release.gpu.global.add.u32 %0, [%1], 1;"
                         : "=r"(cnt) : "l"(&g_count) : "memory");
            s_is_last = (cnt == (unsigned int)(NBLOCKS - 1));
        }
    }
    __syncthreads();

    // ---- fused finalize: last block reduces all block partials ----
    if (s_is_last) {
        asm volatile("fence.acquire.gpu;" ::: "memory");
        volatile float* gp = g_partials;
        float tacc = 0.0f;
#pragma unroll
        for (int j = 0; j < NBLOCKS / THREADS; j++)     // 8 iterations
            tacc += gp[threadIdx.x + j * THREADS];

        __shared__ float s_red[THREADS];
        s_red[threadIdx.x] = tacc;
        __syncthreads();
#pragma unroll
        for (int step = THREADS / 2; step > 0; step >>= 1) {
            if (threadIdx.x < step) s_red[threadIdx.x] += s_red[threadIdx.x + step];
            __syncthreads();
        }
        if (threadIdx.x == 0) {
            out[0]  = s_red[0] / (float)B_EX;
            g_count = 0;                   // reset for next graph replay
        }
    }
}

extern "C" void kernel_launch(void* const* d_in, const int* in_sizes, int n_in,
                              void* d_out, int out_size)
{
    const int*    input_word   = (const int*)   d_in[0];
    const int*    context_word = (const int*)   d_in[1];
    const int*    noise_words  = (const int*)   d_in[2];
    const float4* W_in         = (const float4*)d_in[3];
    const float4* W_ctx        = (const float4*)d_in[4];
    float* out = (float*)d_out;

    w2v_fused_kernel<<<NBLOCKS, THREADS>>>(input_word, context_word,
                                           noise_words, W_in, W_ctx, out);
}